// round 12
// baseline (speedup 1.0000x reference)
#include <cuda_runtime.h>
#include <cuda_bf16.h>
#include <cstdint>

// PINODEv3 persistent RK4 integrator. bf16 m16n8k16 hidden GEMMs.
// R12: Mr=16 rows / NT=128 threads (4 warps, each owns 16x64 C-slab),
// 4 independent CTAs per SM to overlap LayerNorm barrier chains.
// One ldmatrix.x4 per k-tile; weights packed in fragment order.

constexpr int Bn   = 8192;
constexpr int Tn   = 32;
constexpr int Hn   = 256;
constexpr int NLm1 = 3;
constexpr int Mr   = 16;      // batch rows per CTA
constexpr int NT   = 128;     // 4 warps
constexpr int HPB  = 132;     // bf16x2 words per activation row (128 + 4 pad)
#define EPSf 1e-5f

// Packed bf16 weights (fragment order), same as R8-R11:
// word idx = ((((L*16 + kt)*8 + w)*32 + lane)*4 + t)*2 + word
//   n = w*32 + t*8 + (lane>>2);  k = kt*16 + word*8 + 2*(lane&3)
__device__ uint32_t g_Wp[NLm1 * Hn * Hn / 2];

__device__ __forceinline__ uint32_t pack_bf16x2(float lo, float hi) {
    uint32_t u;
    asm("cvt.rn.bf16x2.f32 %0, %1, %2;" : "=r"(u) : "f"(hi), "f"(lo));
    return u;
}
__device__ __forceinline__ float bf_lo(uint32_t u) { return __uint_as_float(u << 16); }
__device__ __forceinline__ float bf_hi(uint32_t u) { return __uint_as_float(u & 0xFFFF0000u); }

__device__ __forceinline__ float silu_t(float v) {
    float t;
    asm("tanh.approx.f32 %0, %1;" : "=f"(t) : "f"(0.5f * v));
    return fmaf(0.5f * v, t, 0.5f * v);   // v * sigmoid(v)
}

__device__ __forceinline__ void mma_bf16(float& c0, float& c1, float& c2, float& c3,
                                         uint32_t a0, uint32_t a1, uint32_t a2, uint32_t a3,
                                         uint32_t b0, uint32_t b1) {
    asm volatile(
        "mma.sync.aligned.m16n8k16.row.col.f32.bf16.bf16.f32 "
        "{%0,%1,%2,%3}, {%4,%5,%6,%7}, {%8,%9}, {%0,%1,%2,%3};"
        : "+f"(c0), "+f"(c1), "+f"(c2), "+f"(c3)
        : "r"(a0), "r"(a1), "r"(a2), "r"(a3), "r"(b0), "r"(b1));
}
__device__ __forceinline__ void ldsm_x4(uint32_t addr, uint32_t& r0, uint32_t& r1,
                                        uint32_t& r2, uint32_t& r3) {
    asm volatile("ldmatrix.sync.aligned.m8n8.x4.shared.b16 {%0,%1,%2,%3}, [%4];"
                 : "=r"(r0), "=r"(r1), "=r"(r2), "=r"(r3) : "r"(addr));
}

__global__ void pack_wh_kernel(const float* __restrict__ Wh) {
    int i = blockIdx.x * blockDim.x + threadIdx.x;
    if (i >= NLm1 * Hn * Hn / 2) return;
    int word = i & 1;
    int t    = (i >> 1) & 3;
    int lane = (i >> 3) & 31;
    int w    = (i >> 8) & 7;
    int kt   = (i >> 11) & 15;
    int L    = i >> 15;
    int n = w * 32 + t * 8 + (lane >> 2);
    int k = kt * 16 + word * 8 + 2 * (lane & 3);
    float lo = Wh[((size_t)L * Hn + k) * Hn + n];
    float hi = Wh[((size_t)L * Hn + k + 1) * Hn + n];
    g_Wp[i] = pack_bf16x2(lo, hi);
}

__global__ void __launch_bounds__(NT, 4) pinode_rk4_tc_kernel(
    const float* __restrict__ y0,
    const float* __restrict__ t_span,
    const float* __restrict__ params,
    const float* __restrict__ W0,
    const float* __restrict__ b0,
    const float* __restrict__ bh,
    const float* __restrict__ ln_g,
    const float* __restrict__ ln_b,
    const float* __restrict__ Wout,
    const float* __restrict__ bout,
    const float* __restrict__ gatep,
    float* __restrict__ out)
{
    __shared__ alignas(16) float sW0[6 * Hn];
    __shared__ alignas(16) float sb0[Hn];
    __shared__ alignas(16) float sbh[NLm1 * Hn];
    __shared__ alignas(16) float sg[4 * Hn];
    __shared__ alignas(16) float sbt[4 * Hn];
    __shared__ float sWout[Hn * 3];
    __shared__ float sbout[3];
    __shared__ float sts[Tn];
    __shared__ alignas(16) uint32_t habf[Mr][HPB];   // bf16x2 activations
    __shared__ alignas(8) float2 pSv[Mr][5];         // LN cross-warp partials
    __shared__ float ysm[Mr][3], psm[Mr][3], yin[Mr][3];
    __shared__ float kacc[Mr][3];
    __shared__ float smu[Mr], srs[Mr];
    __shared__ float sgate;

    const int tid  = threadIdx.x;
    const int lane = tid & 31;
    const int wid  = tid >> 5;        // 0..3
    const int g8   = lane >> 2;
    const int t4   = lane & 3;
    const int row0 = blockIdx.x * Mr;
    const int nbase = 64 * wid;       // 64 columns per warp

    // ldmatrix per-lane address: row = lane&15, word offset 4*(lane>>4)
    const uint32_t habf_u32 = (uint32_t)__cvta_generic_to_shared(&habf[0][0]);
    const uint32_t aBase = habf_u32 + (uint32_t)(((lane & 15) * HPB + 4 * (lane >> 4)) * 4);

    // ---- preload params ----
    for (int i = tid; i < 6 * Hn; i += NT) sW0[i] = W0[i];
    for (int i = tid; i < Hn; i += NT)     sb0[i] = b0[i];
    for (int i = tid; i < NLm1 * Hn; i += NT) sbh[i] = bh[i];
    for (int i = tid; i < 4 * Hn; i += NT) { sg[i] = ln_g[i]; sbt[i] = ln_b[i]; }
    for (int i = tid; i < Hn * 3; i += NT) sWout[i] = Wout[i];
    if (tid < 3)  sbout[tid] = bout[tid];
    if (tid < Tn) sts[tid]  = t_span[tid];
    if (tid == 0) sgate = gatep[0];
    for (int i = tid; i < Mr * 3; i += NT) {
        int m = i / 3, c = i % 3;
        float v = y0[(row0 + m) * 3 + c];
        ysm[m][c] = v;
        yin[m][c] = v;
        psm[m][c] = params[(row0 + m) * 3 + c];
        out[(size_t)(row0 + m) * 3 + c] = v;
    }
    __syncthreads();

    const float gate = sgate;

    // ---- fused LN + SiLU epilogue on C fragments -> habf (bf16x2) ----
    // c[t][e]: t = n-tile (0..7), e: {2h, 2h+1}, rows r = 8h + g8.
    auto fused_ln_epi = [&](float (&c)[8][4], int lnrow) {
        #pragma unroll
        for (int h = 0; h < 2; h++) {
            float s = 0.f, s2 = 0.f;
            #pragma unroll
            for (int t = 0; t < 8; t++) {
                float v0 = c[t][2 * h], v1 = c[t][2 * h + 1];
                s += v0 + v1;
                s2 = fmaf(v0, v0, fmaf(v1, v1, s2));
            }
            s  += __shfl_xor_sync(0xFFFFFFFFu, s, 1);
            s  += __shfl_xor_sync(0xFFFFFFFFu, s, 2);
            s2 += __shfl_xor_sync(0xFFFFFFFFu, s2, 1);
            s2 += __shfl_xor_sync(0xFFFFFFFFu, s2, 2);
            if (t4 == 0) pSv[8 * h + g8][wid] = make_float2(s, s2);
        }
        __syncthreads();
        if (tid < Mr) {
            float s = 0.f, s2 = 0.f;
            #pragma unroll
            for (int w = 0; w < 4; w++) {
                float2 p = pSv[tid][w];
                s += p.x; s2 += p.y;
            }
            float mu  = s * (1.f / Hn);
            float var = s2 * (1.f / Hn) - mu * mu;
            smu[tid] = mu;
            srs[tid] = rsqrtf(var + EPSf);
        }
        __syncthreads();
        #pragma unroll
        for (int h = 0; h < 2; h++) {
            int r = 8 * h + g8;
            float mu = smu[r], rs = srs[r];
            #pragma unroll
            for (int t = 0; t < 8; t++) {
                float2 gv = *reinterpret_cast<const float2*>(&sg[lnrow * Hn + nbase + 8 * t + 2 * t4]);
                float2 bv = *reinterpret_cast<const float2*>(&sbt[lnrow * Hn + nbase + 8 * t + 2 * t4]);
                float v0 = silu_t(fmaf((c[t][2 * h]     - mu) * rs, gv.x, bv.x));
                float v1 = silu_t(fmaf((c[t][2 * h + 1] - mu) * rs, gv.y, bv.y));
                habf[r][32 * wid + 4 * t + t4] = pack_bf16x2(v0, v1);
            }
        }
        __syncthreads();
    };

    // ---- one f_total eval + RK4 stage update (stage in 0..3) ----
    auto eval_f = [&](int stage, float dt, int t) {
        float c[8][4];

        // ===== layer 0 in fragment layout: C = [y,p] @ W0 + b0 =====
        #pragma unroll
        for (int t_ = 0; t_ < 8; t_++) {
            float2 bb = *reinterpret_cast<const float2*>(&sb0[nbase + 8 * t_ + 2 * t4]);
            c[t_][0] = bb.x; c[t_][1] = bb.y;
            c[t_][2] = bb.x; c[t_][3] = bb.y;
        }
        #pragma unroll
        for (int k = 0; k < 6; k++) {
            float x0 = (k < 3) ? yin[g8][k]     : psm[g8][k - 3];
            float x1 = (k < 3) ? yin[8 + g8][k] : psm[8 + g8][k - 3];
            #pragma unroll
            for (int t_ = 0; t_ < 8; t_++) {
                float2 wv = *reinterpret_cast<const float2*>(&sW0[k * Hn + nbase + 8 * t_ + 2 * t4]);
                c[t_][0] = fmaf(x0, wv.x, c[t_][0]);
                c[t_][1] = fmaf(x0, wv.y, c[t_][1]);
                c[t_][2] = fmaf(x1, wv.x, c[t_][2]);
                c[t_][3] = fmaf(x1, wv.y, c[t_][3]);
            }
        }
        fused_ln_epi(c, 0);

        // ===== hidden layers =====
        #pragma unroll 1
        for (int L = 0; L < NLm1; L++) {
            // per-lane base in packed weights (uint4 units); kt stride = 512
            const uint4* Wp = reinterpret_cast<const uint4*>(g_Wp)
                            + (size_t)(L * 16 * 8 + 2 * wid) * 64 + lane * 2;
            #pragma unroll
            for (int t_ = 0; t_ < 8; t_++) {
                float2 bb = *reinterpret_cast<const float2*>(&sbh[L * Hn + nbase + 8 * t_ + 2 * t4]);
                c[t_][0] = bb.x; c[t_][1] = bb.y;
                c[t_][2] = bb.x; c[t_][3] = bb.y;
            }

            uint32_t a0, a1, a2, a3, p0, p1, p2, p3;
            uint4 bc0 = __ldg(Wp), bc1 = __ldg(Wp + 1);
            uint4 bc2 = __ldg(Wp + 64), bc3 = __ldg(Wp + 65);
            ldsm_x4(aBase, a0, a1, a2, a3);

            #pragma unroll
            for (int kt = 0; kt < 16; kt++) {
                uint4 bn0, bn1, bn2, bn3;
                if (kt + 1 < 16) {
                    const uint4* Wn = Wp + (kt + 1) * 512;
                    bn0 = __ldg(Wn);      bn1 = __ldg(Wn + 1);
                    bn2 = __ldg(Wn + 64); bn3 = __ldg(Wn + 65);
                    ldsm_x4(aBase + (kt + 1) * 32, p0, p1, p2, p3);
                }
                mma_bf16(c[0][0], c[0][1], c[0][2], c[0][3], a0, a1, a2, a3, bc0.x, bc0.y);
                mma_bf16(c[1][0], c[1][1], c[1][2], c[1][3], a0, a1, a2, a3, bc0.z, bc0.w);
                mma_bf16(c[2][0], c[2][1], c[2][2], c[2][3], a0, a1, a2, a3, bc1.x, bc1.y);
                mma_bf16(c[3][0], c[3][1], c[3][2], c[3][3], a0, a1, a2, a3, bc1.z, bc1.w);
                mma_bf16(c[4][0], c[4][1], c[4][2], c[4][3], a0, a1, a2, a3, bc2.x, bc2.y);
                mma_bf16(c[5][0], c[5][1], c[5][2], c[5][3], a0, a1, a2, a3, bc2.z, bc2.w);
                mma_bf16(c[6][0], c[6][1], c[6][2], c[6][3], a0, a1, a2, a3, bc3.x, bc3.y);
                mma_bf16(c[7][0], c[7][1], c[7][2], c[7][3], a0, a1, a2, a3, bc3.z, bc3.w);
                if (kt + 1 < 16) {
                    a0 = p0; a1 = p1; a2 = p2; a3 = p3;
                    bc0 = bn0; bc1 = bn1; bc2 = bn2; bc3 = bn3;
                }
            }
            fused_ln_epi(c, L + 1);
        }

        // ===== output projection + Bloch RHS + RK4 stage update =====
        for (int m = wid; m < Mr; m += 4) {
            float s0 = 0.f, s1 = 0.f, s2 = 0.f;
            #pragma unroll
            for (int i = 0; i < 4; i++) {
                int wI = lane + 32 * i;
                uint32_t pw = habf[m][wI];
                float lo = bf_lo(pw), hi = bf_hi(pw);
                s0 = fmaf(lo, sWout[(2 * wI) * 3 + 0], s0);
                s1 = fmaf(lo, sWout[(2 * wI) * 3 + 1], s1);
                s2 = fmaf(lo, sWout[(2 * wI) * 3 + 2], s2);
                s0 = fmaf(hi, sWout[(2 * wI + 1) * 3 + 0], s0);
                s1 = fmaf(hi, sWout[(2 * wI + 1) * 3 + 1], s1);
                s2 = fmaf(hi, sWout[(2 * wI + 1) * 3 + 2], s2);
            }
            #pragma unroll
            for (int o = 16; o; o >>= 1) {
                s0 += __shfl_xor_sync(0xFFFFFFFFu, s0, o);
                s1 += __shfl_xor_sync(0xFFFFFFFFu, s1, o);
                s2 += __shfl_xor_sync(0xFFFFFFFFu, s2, o);
            }
            if (lane == 0) {
                float u = yin[m][0], v = yin[m][1], w = yin[m][2];
                float Om = psm[m][0], ga = psm[m][2];
                float k0 = fmaf(gate, s0 + sbout[0], -ga * u);
                float k1 = fmaf(gate, s1 + sbout[1], -ga * v - Om * w);
                float k2 = fmaf(gate, s2 + sbout[2], -2.f * ga * (w + 1.f) + Om * v);
                float ya = ysm[m][0], yb = ysm[m][1], yc = ysm[m][2];
                if (stage < 3) {
                    if (stage == 0) {
                        kacc[m][0] = k0; kacc[m][1] = k1; kacc[m][2] = k2;
                    } else {
                        kacc[m][0] += 2.f * k0; kacc[m][1] += 2.f * k1; kacc[m][2] += 2.f * k2;
                    }
                    float f = (stage == 2) ? dt : 0.5f * dt;
                    yin[m][0] = fmaf(f, k0, ya);
                    yin[m][1] = fmaf(f, k1, yb);
                    yin[m][2] = fmaf(f, k2, yc);
                } else {
                    float c6 = dt * (1.f / 6.f);
                    float y0n = fmaf(c6, kacc[m][0] + k0, ya);
                    float y1n = fmaf(c6, kacc[m][1] + k1, yb);
                    float y2n = fmaf(c6, kacc[m][2] + k2, yc);
                    ysm[m][0] = y0n; ysm[m][1] = y1n; ysm[m][2] = y2n;
                    yin[m][0] = y0n; yin[m][1] = y1n; yin[m][2] = y2n;
                    size_t idx = ((size_t)(t + 1) * Bn + row0 + m) * 3;
                    out[idx] = y0n; out[idx + 1] = y1n; out[idx + 2] = y2n;
                }
            }
        }
        __syncthreads();
    };

    // ---- RK4 time loop ----
    #pragma unroll 1
    for (int t = 0; t < Tn - 1; t++) {
        float dt = sts[t + 1] - sts[t];
        #pragma unroll 1
        for (int s = 0; s < 4; s++) eval_f(s, dt, t);
    }
}

extern "C" void kernel_launch(void* const* d_in, const int* in_sizes, int n_in,
                              void* d_out, int out_size) {
    (void)in_sizes; (void)n_in; (void)out_size;
    const int nW = NLm1 * Hn * Hn / 2;
    pack_wh_kernel<<<(nW + 255) / 256, 256>>>((const float*)d_in[5]);
    pinode_rk4_tc_kernel<<<Bn / Mr, NT>>>(
        (const float*)d_in[0],   // y0
        (const float*)d_in[1],   // t_span
        (const float*)d_in[2],   // params
        (const float*)d_in[3],   // W0
        (const float*)d_in[4],   // b0
        (const float*)d_in[6],   // bh
        (const float*)d_in[7],   // ln_g
        (const float*)d_in[8],   // ln_b
        (const float*)d_in[9],   // Wout
        (const float*)d_in[10],  // bout
        (const float*)d_in[11],  // gate
        (float*)d_out);
}

// round 15
// speedup vs baseline: 1.2061x; 1.2061x over previous
#include <cuda_runtime.h>
#include <cuda_bf16.h>
#include <cstdint>

// PINODEv3 persistent RK4 integrator. bf16 m16n8k16 hidden GEMMs, ldmatrix
// A-frags pipelined one k-tile ahead, layer0 in fragment layout, register-
// fused LN+SiLU epilogue with REDUNDANT per-warp stats (2 barriers per
// epilogue instead of 3, no serialized single-warp stage). R11 CTA shape:
// Mr=32, NT=256, 2 CTAs/SM.

constexpr int Bn   = 8192;
constexpr int Tn   = 32;
constexpr int Hn   = 256;
constexpr int NLm1 = 3;
constexpr int Mr   = 32;      // batch rows per CTA
constexpr int NT   = 256;     // 8 warps
constexpr int HPB  = 132;     // bf16x2 words per activation row (128 + 4 pad)
#define EPSf 1e-5f

// Packed bf16 weights (fragment order), same as R8-R11:
// word idx = ((((L*16 + kt)*8 + w)*32 + lane)*4 + t)*2 + word
__device__ uint32_t g_Wp[NLm1 * Hn * Hn / 2];

__device__ __forceinline__ uint32_t pack_bf16x2(float lo, float hi) {
    uint32_t u;
    asm("cvt.rn.bf16x2.f32 %0, %1, %2;" : "=r"(u) : "f"(hi), "f"(lo));
    return u;
}
__device__ __forceinline__ float bf_lo(uint32_t u) { return __uint_as_float(u << 16); }
__device__ __forceinline__ float bf_hi(uint32_t u) { return __uint_as_float(u & 0xFFFF0000u); }

__device__ __forceinline__ float silu_t(float v) {
    float t;
    asm("tanh.approx.f32 %0, %1;" : "=f"(t) : "f"(0.5f * v));
    return fmaf(0.5f * v, t, 0.5f * v);   // v * sigmoid(v)
}

__device__ __forceinline__ void mma_bf16(float& c0, float& c1, float& c2, float& c3,
                                         uint32_t a0, uint32_t a1, uint32_t a2, uint32_t a3,
                                         uint32_t b0, uint32_t b1) {
    asm volatile(
        "mma.sync.aligned.m16n8k16.row.col.f32.bf16.bf16.f32 "
        "{%0,%1,%2,%3}, {%4,%5,%6,%7}, {%8,%9}, {%0,%1,%2,%3};"
        : "+f"(c0), "+f"(c1), "+f"(c2), "+f"(c3)
        : "r"(a0), "r"(a1), "r"(a2), "r"(a3), "r"(b0), "r"(b1));
}
__device__ __forceinline__ void ldsm_x4(uint32_t addr, uint32_t& r0, uint32_t& r1,
                                        uint32_t& r2, uint32_t& r3) {
    asm volatile("ldmatrix.sync.aligned.m8n8.x4.shared.b16 {%0,%1,%2,%3}, [%4];"
                 : "=r"(r0), "=r"(r1), "=r"(r2), "=r"(r3) : "r"(addr));
}

__global__ void pack_wh_kernel(const float* __restrict__ Wh) {
    int i = blockIdx.x * blockDim.x + threadIdx.x;
    if (i >= NLm1 * Hn * Hn / 2) return;
    int word = i & 1;
    int t    = (i >> 1) & 3;
    int lane = (i >> 3) & 31;
    int w    = (i >> 8) & 7;
    int kt   = (i >> 11) & 15;
    int L    = i >> 15;
    int n = w * 32 + t * 8 + (lane >> 2);
    int k = kt * 16 + word * 8 + 2 * (lane & 3);
    float lo = Wh[((size_t)L * Hn + k) * Hn + n];
    float hi = Wh[((size_t)L * Hn + k + 1) * Hn + n];
    g_Wp[i] = pack_bf16x2(lo, hi);
}

__global__ void __launch_bounds__(NT, 2) pinode_rk4_tc_kernel(
    const float* __restrict__ y0,
    const float* __restrict__ t_span,
    const float* __restrict__ params,
    const float* __restrict__ W0,
    const float* __restrict__ b0,
    const float* __restrict__ bh,
    const float* __restrict__ ln_g,
    const float* __restrict__ ln_b,
    const float* __restrict__ Wout,
    const float* __restrict__ bout,
    const float* __restrict__ gatep,
    float* __restrict__ out)
{
    __shared__ alignas(16) float sW0[6 * Hn];
    __shared__ alignas(16) float sb0[Hn];
    __shared__ alignas(16) float sbh[NLm1 * Hn];
    __shared__ alignas(16) float sg[4 * Hn];
    __shared__ alignas(16) float sbt[4 * Hn];
    __shared__ float sWout[Hn * 3];
    __shared__ float sbout[3];
    __shared__ float sts[Tn];
    __shared__ alignas(16) uint32_t habf[Mr][HPB];   // bf16x2 activations
    __shared__ alignas(8) float2 pSv[Mr][9];         // LN cross-warp partials
    __shared__ float ysm[Mr][3], psm[Mr][3], yin[Mr][3];
    __shared__ float kacc[Mr][3];
    __shared__ float sgate;

    const int tid  = threadIdx.x;
    const int lane = tid & 31;
    const int wid  = tid >> 5;
    const int g8   = lane >> 2;
    const int t4   = lane & 3;
    const int row0 = blockIdx.x * Mr;
    const int nbase = 32 * wid;

    // ldmatrix per-lane A address (i=0 tile); i=1 tile at +16*HPB*4
    const uint32_t habf_u32 = (uint32_t)__cvta_generic_to_shared(&habf[0][0]);
    const uint32_t aBase = habf_u32
        + (uint32_t)(((8 * ((lane >> 3) & 1) + (lane & 7)) * HPB + 4 * (lane >> 4)) * 4);

    // ---- preload params ----
    for (int i = tid; i < 6 * Hn; i += NT) sW0[i] = W0[i];
    for (int i = tid; i < Hn; i += NT)     sb0[i] = b0[i];
    for (int i = tid; i < NLm1 * Hn; i += NT) sbh[i] = bh[i];
    for (int i = tid; i < 4 * Hn; i += NT) { sg[i] = ln_g[i]; sbt[i] = ln_b[i]; }
    for (int i = tid; i < Hn * 3; i += NT) sWout[i] = Wout[i];
    if (tid < 3)  sbout[tid] = bout[tid];
    if (tid < Tn) sts[tid]  = t_span[tid];
    if (tid == 0) sgate = gatep[0];
    for (int i = tid; i < Mr * 3; i += NT) {
        int m = i / 3, c = i % 3;
        float v = y0[(row0 + m) * 3 + c];
        ysm[m][c] = v;
        yin[m][c] = v;
        psm[m][c] = params[(row0 + m) * 3 + c];
        out[(size_t)(row0 + m) * 3 + c] = v;
    }
    __syncthreads();

    const float gate = sgate;

    // ---- fused LN + SiLU epilogue on C fragments -> habf (bf16x2) ----
    // 2 barriers: partials -> bar -> redundant per-lane stats + shfl + apply -> bar
    auto fused_ln_epi = [&](float (&c)[2][4][4], int lnrow) {
        #pragma unroll
        for (int q = 0; q < 4; q++) {
            int i = q >> 1, h = q & 1;
            float s = 0.f, s2 = 0.f;
            #pragma unroll
            for (int t = 0; t < 4; t++) {
                float v0 = c[i][t][2 * h], v1 = c[i][t][2 * h + 1];
                s += v0 + v1;
                s2 = fmaf(v0, v0, fmaf(v1, v1, s2));
            }
            s  += __shfl_xor_sync(0xFFFFFFFFu, s, 1);
            s  += __shfl_xor_sync(0xFFFFFFFFu, s, 2);
            s2 += __shfl_xor_sync(0xFFFFFFFFu, s2, 1);
            s2 += __shfl_xor_sync(0xFFFFFFFFu, s2, 2);
            if (t4 == 0) {
                int r = 16 * i + 8 * h + g8;
                pSv[r][wid] = make_float2(s, s2);
            }
        }
        __syncthreads();
        // every warp redundantly computes stats for row = lane
        float s = 0.f, s2 = 0.f;
        #pragma unroll
        for (int w = 0; w < 8; w++) {
            float2 p = pSv[lane][w];
            s += p.x; s2 += p.y;
        }
        float mu  = s * (1.f / Hn);
        float var = s2 * (1.f / Hn) - mu * mu;
        float rs  = rsqrtf(var + EPSf);

        float2 gv[4], bv[4];
        #pragma unroll
        for (int t = 0; t < 4; t++) {
            gv[t] = *reinterpret_cast<const float2*>(&sg[lnrow * Hn + nbase + 8 * t + 2 * t4]);
            bv[t] = *reinterpret_cast<const float2*>(&sbt[lnrow * Hn + nbase + 8 * t + 2 * t4]);
        }
        #pragma unroll
        for (int q = 0; q < 4; q++) {
            int i = q >> 1, h = q & 1;
            int r = 16 * i + 8 * h + g8;
            float muq = __shfl_sync(0xFFFFFFFFu, mu, r);
            float rsq = __shfl_sync(0xFFFFFFFFu, rs, r);
            #pragma unroll
            for (int t = 0; t < 4; t++) {
                float v0 = silu_t(fmaf((c[i][t][2 * h]     - muq) * rsq, gv[t].x, bv[t].x));
                float v1 = silu_t(fmaf((c[i][t][2 * h + 1] - muq) * rsq, gv[t].y, bv[t].y));
                habf[r][16 * wid + 4 * t + t4] = pack_bf16x2(v0, v1);
            }
        }
        __syncthreads();
    };

    // ---- one f_total eval + RK4 stage update (stage in 0..3) ----
    auto eval_f = [&](int stage, float dt, int t) {
        float c[2][4][4];

        // ===== layer 0 in fragment layout: C = [y,p] @ W0 + b0 =====
        #pragma unroll
        for (int t_ = 0; t_ < 4; t_++) {
            float2 bb = *reinterpret_cast<const float2*>(&sb0[nbase + 8 * t_ + 2 * t4]);
            c[0][t_][0] = bb.x; c[0][t_][1] = bb.y;
            c[0][t_][2] = bb.x; c[0][t_][3] = bb.y;
            c[1][t_][0] = bb.x; c[1][t_][1] = bb.y;
            c[1][t_][2] = bb.x; c[1][t_][3] = bb.y;
        }
        #pragma unroll
        for (int k = 0; k < 6; k++) {
            float xv[4];
            #pragma unroll
            for (int q = 0; q < 4; q++) {
                int r = 16 * (q >> 1) + 8 * (q & 1) + g8;
                xv[q] = (k < 3) ? yin[r][k] : psm[r][k - 3];
            }
            #pragma unroll
            for (int t_ = 0; t_ < 4; t_++) {
                float2 wv = *reinterpret_cast<const float2*>(&sW0[k * Hn + nbase + 8 * t_ + 2 * t4]);
                #pragma unroll
                for (int q = 0; q < 4; q++) {
                    int i = q >> 1, h = q & 1;
                    c[i][t_][2 * h]     = fmaf(xv[q], wv.x, c[i][t_][2 * h]);
                    c[i][t_][2 * h + 1] = fmaf(xv[q], wv.y, c[i][t_][2 * h + 1]);
                }
            }
        }
        fused_ln_epi(c, 0);

        // ===== hidden layers =====
        #pragma unroll 1
        for (int L = 0; L < NLm1; L++) {
            const uint4* Wp = reinterpret_cast<const uint4*>(g_Wp)
                            + ((size_t)((L * 16) * 8 + wid) * 32 + lane) * 2;
            #pragma unroll
            for (int t_ = 0; t_ < 4; t_++) {
                float2 bb = *reinterpret_cast<const float2*>(&sbh[L * Hn + nbase + 8 * t_ + 2 * t4]);
                c[0][t_][0] = bb.x; c[0][t_][1] = bb.y;
                c[0][t_][2] = bb.x; c[0][t_][3] = bb.y;
                c[1][t_][0] = bb.x; c[1][t_][1] = bb.y;
                c[1][t_][2] = bb.x; c[1][t_][3] = bb.y;
            }

            uint32_t acur[2][4], anext[2][4];
            uint4 bc0 = __ldg(Wp), bc1 = __ldg(Wp + 1);
            ldsm_x4(aBase,                acur[0][0], acur[0][1], acur[0][2], acur[0][3]);
            ldsm_x4(aBase + 16 * HPB * 4, acur[1][0], acur[1][1], acur[1][2], acur[1][3]);

            #pragma unroll
            for (int kt = 0; kt < 16; kt++) {
                uint4 bn0, bn1;
                if (kt + 1 < 16) {
                    bn0 = __ldg(Wp + (kt + 1) * 512);
                    bn1 = __ldg(Wp + (kt + 1) * 512 + 1);
                    ldsm_x4(aBase + (kt + 1) * 32,
                            anext[0][0], anext[0][1], anext[0][2], anext[0][3]);
                    ldsm_x4(aBase + (kt + 1) * 32 + 16 * HPB * 4,
                            anext[1][0], anext[1][1], anext[1][2], anext[1][3]);
                }
                #pragma unroll
                for (int i = 0; i < 2; i++) {
                    mma_bf16(c[i][0][0], c[i][0][1], c[i][0][2], c[i][0][3],
                             acur[i][0], acur[i][1], acur[i][2], acur[i][3], bc0.x, bc0.y);
                    mma_bf16(c[i][1][0], c[i][1][1], c[i][1][2], c[i][1][3],
                             acur[i][0], acur[i][1], acur[i][2], acur[i][3], bc0.z, bc0.w);
                    mma_bf16(c[i][2][0], c[i][2][1], c[i][2][2], c[i][2][3],
                             acur[i][0], acur[i][1], acur[i][2], acur[i][3], bc1.x, bc1.y);
                    mma_bf16(c[i][3][0], c[i][3][1], c[i][3][2], c[i][3][3],
                             acur[i][0], acur[i][1], acur[i][2], acur[i][3], bc1.z, bc1.w);
                }
                if (kt + 1 < 16) {
                    #pragma unroll
                    for (int i = 0; i < 2; i++)
                        #pragma unroll
                        for (int e = 0; e < 4; e++) acur[i][e] = anext[i][e];
                    bc0 = bn0; bc1 = bn1;
                }
            }
            fused_ln_epi(c, L + 1);
        }

        // ===== output projection + Bloch RHS + RK4 stage update =====
        for (int m = wid; m < Mr; m += 8) {
            float s0 = 0.f, s1 = 0.f, s2 = 0.f;
            #pragma unroll
            for (int i = 0; i < 4; i++) {
                int wI = lane + 32 * i;
                uint32_t pw = habf[m][wI];
                float lo = bf_lo(pw), hi = bf_hi(pw);
                s0 = fmaf(lo, sWout[(2 * wI) * 3 + 0], s0);
                s1 = fmaf(lo, sWout[(2 * wI) * 3 + 1], s1);
                s2 = fmaf(lo, sWout[(2 * wI) * 3 + 2], s2);
                s0 = fmaf(hi, sWout[(2 * wI + 1) * 3 + 0], s0);
                s1 = fmaf(hi, sWout[(2 * wI + 1) * 3 + 1], s1);
                s2 = fmaf(hi, sWout[(2 * wI + 1) * 3 + 2], s2);
            }
            #pragma unroll
            for (int o = 16; o; o >>= 1) {
                s0 += __shfl_xor_sync(0xFFFFFFFFu, s0, o);
                s1 += __shfl_xor_sync(0xFFFFFFFFu, s1, o);
                s2 += __shfl_xor_sync(0xFFFFFFFFu, s2, o);
            }
            if (lane == 0) {
                float u = yin[m][0], v = yin[m][1], w = yin[m][2];
                float Om = psm[m][0], ga = psm[m][2];
                float k0 = fmaf(gate, s0 + sbout[0], -ga * u);
                float k1 = fmaf(gate, s1 + sbout[1], -ga * v - Om * w);
                float k2 = fmaf(gate, s2 + sbout[2], -2.f * ga * (w + 1.f) + Om * v);
                float ya = ysm[m][0], yb = ysm[m][1], yc = ysm[m][2];
                if (stage < 3) {
                    if (stage == 0) {
                        kacc[m][0] = k0; kacc[m][1] = k1; kacc[m][2] = k2;
                    } else {
                        kacc[m][0] += 2.f * k0; kacc[m][1] += 2.f * k1; kacc[m][2] += 2.f * k2;
                    }
                    float f = (stage == 2) ? dt : 0.5f * dt;
                    yin[m][0] = fmaf(f, k0, ya);
                    yin[m][1] = fmaf(f, k1, yb);
                    yin[m][2] = fmaf(f, k2, yc);
                } else {
                    float c6 = dt * (1.f / 6.f);
                    float y0n = fmaf(c6, kacc[m][0] + k0, ya);
                    float y1n = fmaf(c6, kacc[m][1] + k1, yb);
                    float y2n = fmaf(c6, kacc[m][2] + k2, yc);
                    ysm[m][0] = y0n; ysm[m][1] = y1n; ysm[m][2] = y2n;
                    yin[m][0] = y0n; yin[m][1] = y1n; yin[m][2] = y2n;
                    size_t idx = ((size_t)(t + 1) * Bn + row0 + m) * 3;
                    out[idx] = y0n; out[idx + 1] = y1n; out[idx + 2] = y2n;
                }
            }
        }
        __syncthreads();
    };

    // ---- RK4 time loop ----
    #pragma unroll 1
    for (int t = 0; t < Tn - 1; t++) {
        float dt = sts[t + 1] - sts[t];
        #pragma unroll 1
        for (int s = 0; s < 4; s++) eval_f(s, dt, t);
    }
}

extern "C" void kernel_launch(void* const* d_in, const int* in_sizes, int n_in,
                              void* d_out, int out_size) {
    (void)in_sizes; (void)n_in; (void)out_size;
    const int nW = NLm1 * Hn * Hn / 2;
    pack_wh_kernel<<<(nW + 255) / 256, 256>>>((const float*)d_in[5]);
    pinode_rk4_tc_kernel<<<Bn / Mr, NT>>>(
        (const float*)d_in[0],   // y0
        (const float*)d_in[1],   // t_span
        (const float*)d_in[2],   // params
        (const float*)d_in[3],   // W0
        (const float*)d_in[4],   // b0
        (const float*)d_in[6],   // bh
        (const float*)d_in[7],   // ln_g
        (const float*)d_in[8],   // ln_b
        (const float*)d_in[9],   // Wout
        (const float*)d_in[10],  // bout
        (const float*)d_in[11],  // gate
        (float*)d_out);
}